// round 13
// baseline (speedup 1.0000x reference)
#include <cuda_runtime.h>
#include <math.h>

#define NS 4096
#define NT 4096
#define RPB 32
#define TPB 128
#define NBLOCKS 1024u
typedef unsigned long long ull;

__device__ double g_acc = 0.0;
__device__ unsigned int g_cnt = 0;

// ---- f32x2 packed helpers (sm_103a) ----
__device__ __forceinline__ ull pk2(float lo, float hi) {
    ull r; asm("mov.b64 %0,{%1,%2};" : "=l"(r) : "f"(lo), "f"(hi)); return r;
}
__device__ __forceinline__ float2 unpk2(ull v) {
    float2 f; asm("mov.b64 {%0,%1},%2;" : "=f"(f.x), "=f"(f.y) : "l"(v)); return f;
}
__device__ __forceinline__ ull fma2_(ull a, ull b, ull c) {
    ull d; asm("fma.rn.f32x2 %0,%1,%2,%3;" : "=l"(d) : "l"(a), "l"(b), "l"(c)); return d;
}
__device__ __forceinline__ ull add2_(ull a, ull b) {
    ull d; asm("add.rn.f32x2 %0,%1,%2;" : "=l"(d) : "l"(a), "l"(b)); return d;
}
__device__ __forceinline__ ull sub2_(ull a, ull b) {
    ull d; asm("sub.rn.f32x2 %0,%1,%2;" : "=l"(d) : "l"(a), "l"(b)); return d;
}
__device__ __forceinline__ ull mul2_(ull a, ull b) {
    ull d; asm("mul.rn.f32x2 %0,%1,%2;" : "=l"(d) : "l"(a), "l"(b)); return d;
}
__device__ __forceinline__ ull clamp2_(ull v) {
    float2 f = unpk2(v);
    f.x = fminf(fmaxf(f.x, -100.0f), 100.0f);
    f.y = fminf(fmaxf(f.y, -100.0f), 100.0f);
    return pk2(f.x, f.y);
}

// one grid row: um = row i-1, cc = row i, up = row i+1 (this thread's 4 cols)
__device__ __forceinline__ void row_accum(
    float4 um, float4 cc, float4 up, float left, float right,
    ull a2, ull nb2, ull nc2, ull nc1,
    ull M2, ull IDT2s,
    bool maskL, bool maskR, bool valid,
    ull& acc0, ull& acc1)
{
    ull um0 = pk2(um.x, um.y), um1 = pk2(um.z, um.w);
    ull cc0 = pk2(cc.x, cc.y), cc1 = pk2(cc.z, cc.w);
    ull up0 = pk2(up.x, up.y), up1 = pk2(up.z, up.w);
    ull cL  = pk2(left, cc.x);
    ull yz  = pk2(cc.y, cc.z);
    ull cR  = pk2(cc.w, right);

    ull Du0  = sub2_(up0, um0);
    ull Du1  = sub2_(up1, um1);
    ull Duu0 = fma2_(cc0, M2, add2_(up0, um0));
    ull Duu1 = fma2_(cc1, M2, add2_(up1, um1));
    ull VSS0 = clamp2_(fma2_(Duu0, a2, mul2_(Du0, nb2)));
    ull VSS1 = clamp2_(fma2_(Duu1, a2, mul2_(Du1, nb2)));
    ull Dt0  = sub2_(yz, cL);
    ull Dt1  = sub2_(cR, yz);

    ull r0 = fma2_(Dt0, IDT2s, cc0);
    r0 = fma2_(VSS0, nc2, r0);
    r0 = fma2_(Du0,  nc1, r0);
    ull r1 = fma2_(Dt1, IDT2s, cc1);
    r1 = fma2_(VSS1, nc2, r1);
    r1 = fma2_(Du1,  nc1, r1);

    if (maskL) { float2 f = unpk2(r0); r0 = pk2(0.0f, f.y); }
    if (maskR) { float2 f = unpk2(r1); r1 = pk2(f.x, 0.0f); }
    if (valid) {
        acc0 = fma2_(r0, r0, acc0);
        acc1 = fma2_(r1, r1, acc1);
    }
}

// compute one 4-row batch (rows base..base+3, base = r0b + k0)
__device__ __forceinline__ void compute_batch(
    int k0, int r0b,
    float4& vm4, float4& vc4,
    float4 v1, float4 v2, float4 v3, float4 v4,
    const float* pe, int dL_off, int dR_off, bool isL, bool isR,
    const ulonglong2* scA, const ulonglong2* scB,
    ull M2, ull IDT2s, bool maskL, bool maskR,
    ull& acc0, ull& acc1)
{
    float eL0 = 0.f, eL1 = 0.f, eL2 = 0.f, eL3 = 0.f;
    float eR0 = 0.f, eR1 = 0.f, eR2 = 0.f, eR3 = 0.f;
    if (isL) {
        eL0 = __ldg(pe + dL_off);
        eL1 = __ldg(pe + NT + dL_off);
        eL2 = __ldg(pe + 2 * NT + dL_off);
        eL3 = __ldg(pe + 3 * NT + dL_off);
    }
    if (isR) {
        eR0 = __ldg(pe + dR_off);
        eR1 = __ldg(pe + NT + dR_off);
        eR2 = __ldg(pe + 2 * NT + dR_off);
        eR3 = __ldg(pe + 3 * NT + dR_off);
    }

    float l0 = __shfl_up_sync(0xffffffffu, vc4.w, 1);
    float r0 = __shfl_down_sync(0xffffffffu, vc4.x, 1);
    float l1 = __shfl_up_sync(0xffffffffu, v1.w, 1);
    float r1 = __shfl_down_sync(0xffffffffu, v1.x, 1);
    float l2 = __shfl_up_sync(0xffffffffu, v2.w, 1);
    float r2 = __shfl_down_sync(0xffffffffu, v2.x, 1);
    float l3 = __shfl_up_sync(0xffffffffu, v3.w, 1);
    float r3 = __shfl_down_sync(0xffffffffu, v3.x, 1);
    if (isL) { l0 = eL0; l1 = eL1; l2 = eL2; l3 = eL3; }
    if (isR) { r0 = eR0; r1 = eR1; r2 = eR2; r3 = eR3; }

    ulonglong2 cA0 = scA[k0],     cB0 = scB[k0];
    ulonglong2 cA1 = scA[k0 + 1], cB1 = scB[k0 + 1];
    ulonglong2 cA2 = scA[k0 + 2], cB2 = scB[k0 + 2];
    ulonglong2 cA3 = scA[k0 + 3], cB3 = scB[k0 + 3];

    bool valid0 = (r0b + k0) != 0;
    bool valid3 = (r0b + k0 + 3) != NS - 1;

    row_accum(vm4, vc4, v1, l0, r0, cA0.x, cA0.y, cB0.x, cB0.y,
              M2, IDT2s, maskL, maskR, valid0, acc0, acc1);
    row_accum(vc4, v1, v2, l1, r1, cA1.x, cA1.y, cB1.x, cB1.y,
              M2, IDT2s, maskL, maskR, true, acc0, acc1);
    row_accum(v1, v2, v3, l2, r2, cA2.x, cA2.y, cB2.x, cB2.y,
              M2, IDT2s, maskL, maskR, true, acc0, acc1);
    row_accum(v2, v3, v4, l3, r3, cA3.x, cA3.y, cB3.x, cB3.y,
              M2, IDT2s, maskL, maskR, valid3, acc0, acc1);

    vm4 = v3;
    vc4 = v4;
}

__global__ __launch_bounds__(TPB, 6) void loss_kernel(const float* __restrict__ V,
                                                      float C1, float dL,
                                                      float* __restrict__ out)
{
    __shared__ ulonglong2 scA[RPB];   // {a2, -b2}
    __shared__ ulonglong2 scB[RPB];   // {-c2*0.4, -c1*0.4}
    __shared__ double ws[TPB / 32];

    const int tid  = threadIdx.x;
    const int lane = tid & 31;
    const int bx   = blockIdx.x;
    const int by   = blockIdx.y;
    const int j0   = bx * (TPB * 4) + tid * 4;   // 4-col chunk
    const int r0b  = by * RPB;

    const float INV2DT = 4095.0f / 0.04f;
    const float INV2DU = 4095.0f * 0.5f;
    const float INVDU2 = 4095.0f * 4095.0f;
    const float RS = 0.4f;

    if (tid < RPB) {
        int i = r0b + tid;
        float u   = (float)i * (1.0f / 4095.0f);
        float L   = fmaf(dL, u, C1);
        float L2  = L * L;
        float S   = fmaf(30.0f, fmaf(L2 * L, (1.0f / 6.0f), L), 100.0f);
        float Sn  = S * (1.0f / 300.0f);
        float Su  = 0.1f * dL * fmaf(0.5f, L2, 1.0f);
        float Suu = 0.1f * dL * dL * L;
        float rSu  = 1.0f / Su;
        float rSu2 = rSu * rSu;
        float a  = INVDU2 * rSu2;
        float b  = INV2DU * Suu * rSu2 * rSu;
        float c2 = Sn * Sn * RS;
        float c1 = 2.5f * Sn * INV2DU * rSu * RS;
        scA[tid] = make_ulonglong2(pk2(a, a),     pk2(-b, -b));
        scB[tid] = make_ulonglong2(pk2(-c2, -c2), pk2(-c1, -c1));
    }
    __syncthreads();

    const bool maskL = (j0 == 0);
    const bool maskR = (j0 + 3 == NT - 1);
    const ull M2    = pk2(-2.0f, -2.0f);
    const ull IDT2s = pk2(INV2DT * RS, INV2DT * RS);

    const int dL_off = (j0 > 0) ? -1 : 0;           // jL - j0
    const int dR_off = (j0 + 4 < NT) ? 4 : 3;       // jR - j0
    const bool isL = (lane == 0);
    const bool isR = (lane == 31);
    const bool lastBlk = (r0b == NS - RPB);

    // pcc = base-row pointer of the batch currently being computed
    const float* pcc = V + j0 + (size_t)r0b * NT;
    const float* pm = (r0b > 0) ? (pcc - NT) : pcc;

    float4 vm4 = *(const float4*)pm;
    float4 vc4 = *(const float4*)pcc;

    ull acc0 = 0ull, acc1 = 0ull;

    // preload batch 0 (rows r0b+1 .. r0b+4) into buffer A
    float4 a1 = *(const float4*)(pcc + NT);
    float4 a2 = *(const float4*)(pcc + 2 * NT);
    float4 a3 = *(const float4*)(pcc + 3 * NT);
    float4 a4 = *(const float4*)(pcc + 4 * NT);
    float4 b1, b2, b3, b4;

    #pragma unroll 1
    for (int kk = 0; kk < 4; ++kk) {
        const int k0 = kk * 8;               // batch 2kk row offset

        // prefetch batch 2kk+1 into B (rows base+5 .. base+8)
        {
            const float* pn = pcc + 4 * NT;
            b1 = *(const float4*)(pn + NT);
            b2 = *(const float4*)(pn + 2 * NT);
            b3 = *(const float4*)(pn + 3 * NT);
            const float* pb4 = (kk == 3 && lastBlk) ? (pn + 3 * NT) : (pn + 4 * NT);
            b4 = *(const float4*)pb4;
        }

        // compute batch 2kk from A
        compute_batch(k0, r0b, vm4, vc4, a1, a2, a3, a4,
                      pcc, dL_off, dR_off, isL, isR, scA, scB,
                      M2, IDT2s, maskL, maskR, acc0, acc1);

        // prefetch batch 2kk+2 into A (doesn't exist for kk==3)
        if (kk < 3) {
            const float* pn2 = pcc + 8 * NT;
            a1 = *(const float4*)(pn2 + NT);
            a2 = *(const float4*)(pn2 + 2 * NT);
            a3 = *(const float4*)(pn2 + 3 * NT);
            a4 = *(const float4*)(pn2 + 4 * NT);
        }

        // compute batch 2kk+1 from B
        compute_batch(k0 + 4, r0b, vm4, vc4, b1, b2, b3, b4,
                      pcc + 4 * NT, dL_off, dR_off, isL, isR, scA, scB,
                      M2, IDT2s, maskL, maskR, acc0, acc1);

        pcc += 8 * NT;
    }

    float2 f0 = unpk2(acc0), f1 = unpk2(acc1);
    double p = ((double)f0.x + (double)f0.y + (double)f1.x + (double)f1.y)
             * (6.25 / (4094.0 * 4094.0));

    // ---- BC / TC tails ----
    if (by == 0 && bx == 0) {
        const float* rowp = V + (size_t)(NS - 1) * NT;
        double s = 0.0;
        for (int t = tid; t < NT; t += TPB) {
            float tn = (float)t * (1.0f / 4095.0f);
            float target = 1.0f - (1.0f / 3.0f) * expf(-0.05f * (1.0f - tn));
            float d = rowp[t] - target;
            s += (double)(d * d);
        }
        p += s * (10.0 / (double)NT);
    } else if (by == 0 && bx == 1) {
        double s = 0.0;
        for (int si = tid; si < NS; si += TPB) {
            float u  = (float)si * (1.0f / 4095.0f);
            float x  = 50.0f * (u - (1.0f / 3.0f));
            float sp = (fmaxf(x, 0.0f) + log1pf(expf(-fabsf(x)))) * (1.0f / 50.0f);
            float d  = V[(size_t)si * NT + (NT - 1)] - sp;
            float ad = fabsf(d);
            float h  = (ad < 0.01f) ? 0.5f * d * d : 0.01f * (ad - 0.005f);
            s += (double)h;
        }
        p += s * (10.0 / (double)NS);
    }

    // ---- block reduce (double) ----
    #pragma unroll
    for (int o = 16; o > 0; o >>= 1)
        p += __shfl_down_sync(0xffffffffu, p, o);
    if (lane == 0) ws[tid >> 5] = p;
    __syncthreads();

    if (tid == 0) {
        double s = 0.0;
        #pragma unroll
        for (int k = 0; k < TPB / 32; ++k) s += ws[k];
        atomicAdd(&g_acc, s);
        __threadfence();
        unsigned int t = atomicAdd(&g_cnt, 1u);
        if (t == NBLOCKS - 1u) {
            double total = atomicAdd(&g_acc, 0.0);
            out[0] = (float)total;
            g_acc = 0.0;
            __threadfence();
            g_cnt = 0u;
        }
    }
}

// Host-side: hyperbolic root of depressed cubic (CubicStretching)
static double solve_depressed_cubic(double Q)
{
    const double p = 6.0;
    const double q = 6.0 * Q;
    double sp = sqrt(p);
    double arg = fabs(q) / (2.0 * p * sp / (3.0 * sqrt(3.0)));
    if (arg < 1.0) arg = 1.0;
    double c = 2.0 * sp * cosh(acosh(arg) / 3.0);
    return (q >= 0.0) ? -c : c;
}

extern "C" void kernel_launch(void* const* d_in, const int* in_sizes, int n_in,
                              void* d_out, int out_size)
{
    const float* V = (const float*)d_in[0];
    float* out = (float*)d_out;

    const double C1 = solve_depressed_cubic((100.0 - 0.0)   / 30.0);
    const double C2 = solve_depressed_cubic((100.0 - 300.0) / 30.0);
    const float C1f = (float)C1;
    const float dLf = (float)(C2 - C1);

    dim3 grid(NT / (TPB * 4), NS / RPB);   // (8, 128) = 1024 blocks
    loss_kernel<<<grid, TPB>>>(V, C1f, dLf, out);
}

// round 14
// speedup vs baseline: 1.0860x; 1.0860x over previous
#include <cuda_runtime.h>
#include <cuda_pipeline.h>
#include <math.h>

#define NS 4096
#define NT 4096
#define RPB 32
#define TPB 128
#define NBLOCKS 1024u
#define SLOTW 520          // 512 cols + halos + pad
#define NSLOT 12
typedef unsigned long long ull;

__device__ double g_acc = 0.0;
__device__ unsigned int g_cnt = 0;

// ---- f32x2 packed helpers (sm_103a) ----
__device__ __forceinline__ ull pk2(float lo, float hi) {
    ull r; asm("mov.b64 %0,{%1,%2};" : "=l"(r) : "f"(lo), "f"(hi)); return r;
}
__device__ __forceinline__ float2 unpk2(ull v) {
    float2 f; asm("mov.b64 {%0,%1},%2;" : "=f"(f.x), "=f"(f.y) : "l"(v)); return f;
}
__device__ __forceinline__ ull fma2_(ull a, ull b, ull c) {
    ull d; asm("fma.rn.f32x2 %0,%1,%2,%3;" : "=l"(d) : "l"(a), "l"(b), "l"(c)); return d;
}
__device__ __forceinline__ ull add2_(ull a, ull b) {
    ull d; asm("add.rn.f32x2 %0,%1,%2;" : "=l"(d) : "l"(a), "l"(b)); return d;
}
__device__ __forceinline__ ull sub2_(ull a, ull b) {
    ull d; asm("sub.rn.f32x2 %0,%1,%2;" : "=l"(d) : "l"(a), "l"(b)); return d;
}
__device__ __forceinline__ ull mul2_(ull a, ull b) {
    ull d; asm("mul.rn.f32x2 %0,%1,%2;" : "=l"(d) : "l"(a), "l"(b)); return d;
}
__device__ __forceinline__ ull clamp2_(ull v) {
    float2 f = unpk2(v);
    f.x = fminf(fmaxf(f.x, -100.0f), 100.0f);
    f.y = fminf(fmaxf(f.y, -100.0f), 100.0f);
    return pk2(f.x, f.y);
}

// one grid row: um = row i-1 (regs), cc = row i (regs), up = row i+1
__device__ __forceinline__ void row_accum(
    float4 um, float4 cc, float4 up, float left, float right,
    ull a2, ull nb2, ull nc2, ull nc1,
    ull M2, ull IDT2s,
    bool maskL, bool maskR, bool valid,
    ull& acc0, ull& acc1)
{
    ull um0 = pk2(um.x, um.y), um1 = pk2(um.z, um.w);
    ull cc0 = pk2(cc.x, cc.y), cc1 = pk2(cc.z, cc.w);
    ull up0 = pk2(up.x, up.y), up1 = pk2(up.z, up.w);
    ull cL  = pk2(left, cc.x);
    ull yz  = pk2(cc.y, cc.z);
    ull cR  = pk2(cc.w, right);

    ull Du0  = sub2_(up0, um0);
    ull Du1  = sub2_(up1, um1);
    ull Duu0 = fma2_(cc0, M2, add2_(up0, um0));
    ull Duu1 = fma2_(cc1, M2, add2_(up1, um1));
    ull VSS0 = clamp2_(fma2_(Duu0, a2, mul2_(Du0, nb2)));
    ull VSS1 = clamp2_(fma2_(Duu1, a2, mul2_(Du1, nb2)));
    ull Dt0  = sub2_(yz, cL);
    ull Dt1  = sub2_(cR, yz);

    ull r0 = fma2_(Dt0, IDT2s, cc0);
    r0 = fma2_(VSS0, nc2, r0);
    r0 = fma2_(Du0,  nc1, r0);
    ull r1 = fma2_(Dt1, IDT2s, cc1);
    r1 = fma2_(VSS1, nc2, r1);
    r1 = fma2_(Du1,  nc1, r1);

    if (maskL) { float2 f = unpk2(r0); r0 = pk2(0.0f, f.y); }
    if (maskR) { float2 f = unpk2(r1); r1 = pk2(f.x, 0.0f); }
    if (valid) {
        acc0 = fma2_(r0, r0, acc0);
        acc1 = fma2_(r1, r1, acc1);
    }
}

// issue one 4-row cp.async group: rows row1..row1+3 into slots slot0..+3 (wrapped)
__device__ __forceinline__ void issue4(float* ring, const float* __restrict__ V,
                                       int row1, int slot0,
                                       int j0blk, int jLb, int jRb,
                                       int toff, int tid)
{
    #pragma unroll
    for (int q = 0; q < 4; ++q) {
        int slot = slot0 + q; if (slot >= NSLOT) slot -= NSLOT;
        int r = row1 + q;     if (r > NS - 1)    r = NS - 1;
        float* dst = ring + slot * SLOTW;
        const float* src = V + (size_t)r * NT;
        __pipeline_memcpy_async(dst + 4 + toff, src + j0blk + toff, 16);
        if (tid == 0)       __pipeline_memcpy_async(dst + 3,   src + jLb, 4);
        if (tid == TPB - 1) __pipeline_memcpy_async(dst + 516, src + jRb, 4);
    }
}

__global__ __launch_bounds__(TPB) void loss_kernel(const float* __restrict__ V,
                                                   float C1, float dL,
                                                   float* __restrict__ out)
{
    __shared__ ulonglong2 scA[RPB];   // {a2, -b2}
    __shared__ ulonglong2 scB[RPB];   // {-c2*0.4, -c1*0.4}
    __shared__ double ws[TPB / 32];
    __shared__ __align__(16) float ring[NSLOT * SLOTW];

    const int tid  = threadIdx.x;
    const int lane = tid & 31;
    const int bx   = blockIdx.x;
    const int by   = blockIdx.y;
    const int j0blk = bx * 512;
    const int toff  = tid * 4;
    const int j0    = j0blk + toff;
    const int r0b   = by * RPB;

    const float INV2DT = 4095.0f / 0.04f;
    const float INV2DU = 4095.0f * 0.5f;
    const float INVDU2 = 4095.0f * 4095.0f;
    const float RS = 0.4f;

    if (tid < RPB) {
        int i = r0b + tid;
        float u   = (float)i * (1.0f / 4095.0f);
        float L   = fmaf(dL, u, C1);
        float L2  = L * L;
        float S   = fmaf(30.0f, fmaf(L2 * L, (1.0f / 6.0f), L), 100.0f);
        float Sn  = S * (1.0f / 300.0f);
        float Su  = 0.1f * dL * fmaf(0.5f, L2, 1.0f);
        float Suu = 0.1f * dL * dL * L;
        float rSu  = 1.0f / Su;
        float rSu2 = rSu * rSu;
        float a  = INVDU2 * rSu2;
        float b  = INV2DU * Suu * rSu2 * rSu;
        float c2 = Sn * Sn * RS;
        float c1 = 2.5f * Sn * INV2DU * rSu * RS;
        scA[tid] = make_ulonglong2(pk2(a, a),     pk2(-b, -b));
        scB[tid] = make_ulonglong2(pk2(-c2, -c2), pk2(-c1, -c1));
    }

    const bool maskL = (j0 == 0);
    const bool maskR = (j0 + 3 == NT - 1);
    const ull M2    = pk2(-2.0f, -2.0f);
    const ull IDT2s = pk2(INV2DT * RS, INV2DT * RS);

    const int jLb = (j0blk > 0) ? j0blk - 1 : 0;
    const int jRb = (j0blk + 512 < NT) ? j0blk + 512 : NT - 1;

    // prologue: issue first two groups (rows r0b+1..r0b+8)
    issue4(ring, V, r0b + 1, 0, j0blk, jLb, jRb, toff, tid);
    __pipeline_commit();
    issue4(ring, V, r0b + 5, 4, j0blk, jLb, jRb, toff, tid);
    __pipeline_commit();

    // seeds: rows r0b-1 (clamped) and r0b + stage-0 halos, direct LDG
    const float* p0 = V + (size_t)r0b * NT;
    float4 vm4 = *(const float4*)(((r0b > 0) ? p0 - NT : p0) + j0);
    float4 vc4 = *(const float4*)(p0 + j0);
    float hl = p0[(j0 > 0) ? j0 - 1 : 0];
    float hr = p0[(j0 + 4 < NT) ? j0 + 4 : NT - 1];

    __syncthreads();   // coeff smem ready

    ull acc0 = 0ull, acc1 = 0ull;
    int sl = 0;        // slot of m = 4s

    #pragma unroll 1
    for (int s = 0; s < 8; ++s) {
        __pipeline_wait_prior(1);
        __syncthreads();

        // halos of first compute row (row r0b+4s); its slot is about to be reused
        float hlc, hrc;
        if (s == 0) { hlc = hl; hrc = hr; }
        else {
            int hs = sl - 1; if (hs < 0) hs += NSLOT;
            hlc = ring[hs * SLOTW + 3 + toff];
            hrc = ring[hs * SLOTW + 8 + toff];
        }
        __syncthreads();   // all halo reads done before new writes can land

        if (s < 6) {
            int w0 = sl + 8; if (w0 >= NSLOT) w0 -= NSLOT;
            issue4(ring, V, r0b + 4 * s + 9, w0, j0blk, jLb, jRb, toff, tid);
        }
        __pipeline_commit();

        int u0 = sl;
        int u1 = sl + 1; if (u1 >= NSLOT) u1 -= NSLOT;
        int u2 = sl + 2; if (u2 >= NSLOT) u2 -= NSLOT;
        int u3 = sl + 3; if (u3 >= NSLOT) u3 -= NSLOT;
        const int k = 4 * s;

        ulonglong2 cA, cB;
        float4 up;
        float lv, rv;

        // row k (first of stage)
        up = *(const float4*)&ring[u0 * SLOTW + 4 + toff];
        cA = scA[k]; cB = scB[k];
        row_accum(vm4, vc4, up, hlc, hrc, cA.x, cA.y, cB.x, cB.y,
                  M2, IDT2s, maskL, maskR, (r0b + k) != 0, acc0, acc1);
        vm4 = vc4; vc4 = up;

        // row k+1
        lv = ring[u0 * SLOTW + 3 + toff]; rv = ring[u0 * SLOTW + 8 + toff];
        up = *(const float4*)&ring[u1 * SLOTW + 4 + toff];
        cA = scA[k + 1]; cB = scB[k + 1];
        row_accum(vm4, vc4, up, lv, rv, cA.x, cA.y, cB.x, cB.y,
                  M2, IDT2s, maskL, maskR, true, acc0, acc1);
        vm4 = vc4; vc4 = up;

        // row k+2
        lv = ring[u1 * SLOTW + 3 + toff]; rv = ring[u1 * SLOTW + 8 + toff];
        up = *(const float4*)&ring[u2 * SLOTW + 4 + toff];
        cA = scA[k + 2]; cB = scB[k + 2];
        row_accum(vm4, vc4, up, lv, rv, cA.x, cA.y, cB.x, cB.y,
                  M2, IDT2s, maskL, maskR, true, acc0, acc1);
        vm4 = vc4; vc4 = up;

        // row k+3
        lv = ring[u2 * SLOTW + 3 + toff]; rv = ring[u2 * SLOTW + 8 + toff];
        up = *(const float4*)&ring[u3 * SLOTW + 4 + toff];
        cA = scA[k + 3]; cB = scB[k + 3];
        row_accum(vm4, vc4, up, lv, rv, cA.x, cA.y, cB.x, cB.y,
                  M2, IDT2s, maskL, maskR, (r0b + k + 3) != NS - 1, acc0, acc1);
        vm4 = vc4; vc4 = up;

        sl += 4; if (sl >= NSLOT) sl -= NSLOT;
    }

    float2 f0 = unpk2(acc0), f1 = unpk2(acc1);
    double p = ((double)f0.x + (double)f0.y + (double)f1.x + (double)f1.y)
             * (6.25 / (4094.0 * 4094.0));

    // ---- BC / TC tails ----
    if (by == 0 && bx == 0) {
        const float* rowp = V + (size_t)(NS - 1) * NT;
        double s = 0.0;
        for (int t = tid; t < NT; t += TPB) {
            float tn = (float)t * (1.0f / 4095.0f);
            float target = 1.0f - (1.0f / 3.0f) * expf(-0.05f * (1.0f - tn));
            float d = rowp[t] - target;
            s += (double)(d * d);
        }
        p += s * (10.0 / (double)NT);
    } else if (by == 0 && bx == 1) {
        double s = 0.0;
        for (int si = tid; si < NS; si += TPB) {
            float u  = (float)si * (1.0f / 4095.0f);
            float x  = 50.0f * (u - (1.0f / 3.0f));
            float sp = (fmaxf(x, 0.0f) + log1pf(expf(-fabsf(x)))) * (1.0f / 50.0f);
            float d  = V[(size_t)si * NT + (NT - 1)] - sp;
            float ad = fabsf(d);
            float h  = (ad < 0.01f) ? 0.5f * d * d : 0.01f * (ad - 0.005f);
            s += (double)h;
        }
        p += s * (10.0 / (double)NS);
    }

    // ---- block reduce (double) ----
    #pragma unroll
    for (int o = 16; o > 0; o >>= 1)
        p += __shfl_down_sync(0xffffffffu, p, o);
    if (lane == 0) ws[tid >> 5] = p;
    __syncthreads();

    if (tid == 0) {
        double s = 0.0;
        #pragma unroll
        for (int k2 = 0; k2 < TPB / 32; ++k2) s += ws[k2];
        atomicAdd(&g_acc, s);
        __threadfence();
        unsigned int t = atomicAdd(&g_cnt, 1u);
        if (t == NBLOCKS - 1u) {
            double total = atomicAdd(&g_acc, 0.0);
            out[0] = (float)total;
            g_acc = 0.0;
            __threadfence();
            g_cnt = 0u;
        }
    }
}

// Host-side: hyperbolic root of depressed cubic (CubicStretching)
static double solve_depressed_cubic(double Q)
{
    const double p = 6.0;
    const double q = 6.0 * Q;
    double sp = sqrt(p);
    double arg = fabs(q) / (2.0 * p * sp / (3.0 * sqrt(3.0)));
    if (arg < 1.0) arg = 1.0;
    double c = 2.0 * sp * cosh(acosh(arg) / 3.0);
    return (q >= 0.0) ? -c : c;
}

extern "C" void kernel_launch(void* const* d_in, const int* in_sizes, int n_in,
                              void* d_out, int out_size)
{
    const float* V = (const float*)d_in[0];
    float* out = (float*)d_out;

    const double C1 = solve_depressed_cubic((100.0 - 0.0)   / 30.0);
    const double C2 = solve_depressed_cubic((100.0 - 300.0) / 30.0);
    const float C1f = (float)C1;
    const float dLf = (float)(C2 - C1);

    dim3 grid(NT / 512, NS / RPB);   // (8, 128) = 1024 blocks
    loss_kernel<<<grid, TPB>>>(V, C1f, dLf, out);
}

// round 15
// speedup vs baseline: 1.0890x; 1.0028x over previous
#include <cuda_runtime.h>
#include <cuda_pipeline.h>
#include <math.h>

#define NS 4096
#define NT 4096
#define RPB 32
#define TPB 128
#define NBLOCKS 1024u
#define SLOTW 520          // 512 cols + halos + pad
#define NSLOT 12
typedef unsigned long long ull;

__device__ double g_acc = 0.0;
__device__ unsigned int g_cnt = 0;

// ---- f32x2 packed helpers (sm_103a) ----
__device__ __forceinline__ ull pk2(float lo, float hi) {
    ull r; asm("mov.b64 %0,{%1,%2};" : "=l"(r) : "f"(lo), "f"(hi)); return r;
}
__device__ __forceinline__ float2 unpk2(ull v) {
    float2 f; asm("mov.b64 {%0,%1},%2;" : "=f"(f.x), "=f"(f.y) : "l"(v)); return f;
}
__device__ __forceinline__ ull fma2_(ull a, ull b, ull c) {
    ull d; asm("fma.rn.f32x2 %0,%1,%2,%3;" : "=l"(d) : "l"(a), "l"(b), "l"(c)); return d;
}
__device__ __forceinline__ ull add2_(ull a, ull b) {
    ull d; asm("add.rn.f32x2 %0,%1,%2;" : "=l"(d) : "l"(a), "l"(b)); return d;
}
__device__ __forceinline__ ull sub2_(ull a, ull b) {
    ull d; asm("sub.rn.f32x2 %0,%1,%2;" : "=l"(d) : "l"(a), "l"(b)); return d;
}
__device__ __forceinline__ ull mul2_(ull a, ull b) {
    ull d; asm("mul.rn.f32x2 %0,%1,%2;" : "=l"(d) : "l"(a), "l"(b)); return d;
}
__device__ __forceinline__ ull clamp2_(ull v) {
    float2 f = unpk2(v);
    f.x = fminf(fmaxf(f.x, -100.0f), 100.0f);
    f.y = fminf(fmaxf(f.y, -100.0f), 100.0f);
    return pk2(f.x, f.y);
}

// one grid row: um = row i-1 (regs), cc = row i (regs), up = row i+1
__device__ __forceinline__ void row_accum(
    float4 um, float4 cc, float4 up, float left, float right,
    ull a2, ull nb2, ull nc2, ull nc1,
    ull M2, ull IDT2s,
    bool maskL, bool maskR, bool valid,
    ull& acc0, ull& acc1)
{
    ull um0 = pk2(um.x, um.y), um1 = pk2(um.z, um.w);
    ull cc0 = pk2(cc.x, cc.y), cc1 = pk2(cc.z, cc.w);
    ull up0 = pk2(up.x, up.y), up1 = pk2(up.z, up.w);
    ull cL  = pk2(left, cc.x);
    ull yz  = pk2(cc.y, cc.z);
    ull cR  = pk2(cc.w, right);

    ull Du0  = sub2_(up0, um0);
    ull Du1  = sub2_(up1, um1);
    ull Duu0 = fma2_(cc0, M2, add2_(up0, um0));
    ull Duu1 = fma2_(cc1, M2, add2_(up1, um1));
    ull VSS0 = clamp2_(fma2_(Duu0, a2, mul2_(Du0, nb2)));
    ull VSS1 = clamp2_(fma2_(Duu1, a2, mul2_(Du1, nb2)));
    ull Dt0  = sub2_(yz, cL);
    ull Dt1  = sub2_(cR, yz);

    ull r0 = fma2_(Dt0, IDT2s, cc0);
    r0 = fma2_(VSS0, nc2, r0);
    r0 = fma2_(Du0,  nc1, r0);
    ull r1 = fma2_(Dt1, IDT2s, cc1);
    r1 = fma2_(VSS1, nc2, r1);
    r1 = fma2_(Du1,  nc1, r1);

    if (maskL) { float2 f = unpk2(r0); r0 = pk2(0.0f, f.y); }
    if (maskR) { float2 f = unpk2(r1); r1 = pk2(f.x, 0.0f); }
    if (valid) {
        acc0 = fma2_(r0, r0, acc0);
        acc1 = fma2_(r1, r1, acc1);
    }
}

// issue one 4-row cp.async group into 4 CONTIGUOUS slots starting at dst0
__device__ __forceinline__ void issue4(float* dst0, const float* __restrict__ V,
                                       int row1,
                                       int j0blk, int jLb, int jRb,
                                       int toff, int tid)
{
    #pragma unroll
    for (int q = 0; q < 4; ++q) {
        int r = row1 + q; if (r > NS - 1) r = NS - 1;
        float* dst = dst0 + q * SLOTW;
        const float* src = V + (size_t)r * NT;
        __pipeline_memcpy_async(dst + 4 + toff, src + j0blk + toff, 16);
        if (tid == 0)       __pipeline_memcpy_async(dst + 3,   src + jLb, 4);
        if (tid == TPB - 1) __pipeline_memcpy_async(dst + 516, src + jRb, 4);
    }
}

__global__ __launch_bounds__(TPB) void loss_kernel(const float* __restrict__ V,
                                                   float C1, float dL,
                                                   float* __restrict__ out)
{
    __shared__ ulonglong2 scA[RPB];   // {a2, -b2}
    __shared__ ulonglong2 scB[RPB];   // {-c2*0.4, -c1*0.4}
    __shared__ double ws[TPB / 32];
    __shared__ __align__(16) float ring[NSLOT * SLOTW];

    const int tid  = threadIdx.x;
    const int lane = tid & 31;
    const int bx   = blockIdx.x;
    const int by   = blockIdx.y;
    const int j0blk = bx * 512;
    const int toff  = tid * 4;
    const int j0    = j0blk + toff;
    const int r0b   = by * RPB;

    const float INV2DT = 4095.0f / 0.04f;
    const float INV2DU = 4095.0f * 0.5f;
    const float INVDU2 = 4095.0f * 4095.0f;
    const float RS = 0.4f;

    if (tid < RPB) {
        int i = r0b + tid;
        float u   = (float)i * (1.0f / 4095.0f);
        float L   = fmaf(dL, u, C1);
        float L2  = L * L;
        float S   = fmaf(30.0f, fmaf(L2 * L, (1.0f / 6.0f), L), 100.0f);
        float Sn  = S * (1.0f / 300.0f);
        float Su  = 0.1f * dL * fmaf(0.5f, L2, 1.0f);
        float Suu = 0.1f * dL * dL * L;
        float rSu  = 1.0f / Su;
        float rSu2 = rSu * rSu;
        float a  = INVDU2 * rSu2;
        float b  = INV2DU * Suu * rSu2 * rSu;
        float c2 = Sn * Sn * RS;
        float c1 = 2.5f * Sn * INV2DU * rSu * RS;
        scA[tid] = make_ulonglong2(pk2(a, a),     pk2(-b, -b));
        scB[tid] = make_ulonglong2(pk2(-c2, -c2), pk2(-c1, -c1));
    }

    const bool maskL = (j0 == 0);
    const bool maskR = (j0 + 3 == NT - 1);
    const ull M2    = pk2(-2.0f, -2.0f);
    const ull IDT2s = pk2(INV2DT * RS, INV2DT * RS);

    const int jLb = (j0blk > 0) ? j0blk - 1 : 0;
    const int jRb = (j0blk + 512 < NT) ? j0blk + 512 : NT - 1;

    // prologue: two groups in flight (rows r0b+1..r0b+8 -> slots 0..7)
    issue4(ring,             V, r0b + 1, j0blk, jLb, jRb, toff, tid);
    __pipeline_commit();
    issue4(ring + 4 * SLOTW, V, r0b + 5, j0blk, jLb, jRb, toff, tid);
    __pipeline_commit();

    // seeds: row r0b-1 (clamped), row r0b, and row-r0b halos via direct LDG
    const float* p0 = V + (size_t)r0b * NT;
    float4 vm4 = *(const float4*)(((r0b > 0) ? p0 - NT : p0) + j0);
    float4 vc4 = *(const float4*)(p0 + j0);
    float hl = p0[(j0 > 0) ? j0 - 1 : 0];
    float hr = p0[(j0 + 4 < NT) ? j0 + 4 : NT - 1];

    __syncthreads();   // coeff smem ready

    ull acc0 = 0ull, acc1 = 0ull;
    int sl = 0;        // base slot of current stage, in {0,4,8}

    #pragma unroll 1
    for (int s = 0; s < 8; ++s) {
        // group s data visible after wait + barrier; barrier also separates
        // stage s-1's ring reads from the prefetch writes issued below
        __pipeline_wait_prior(1);
        __syncthreads();

        if (s < 6) {
            int w0 = (sl + 8 >= NSLOT) ? sl - 4 : sl + 8;   // 4 contiguous slots
            issue4(ring + w0 * SLOTW, V, r0b + 4 * s + 9, j0blk, jLb, jRb, toff, tid);
        }
        __pipeline_commit();   // empty group at s>=6 keeps wait_prior(1) correct

        const float* rs = ring + sl * SLOTW;
        const int k = 4 * s;
        ulonglong2 cA, cB;
        float4 up;
        float lv, rv;

        // row k: halos carried in registers (hl,hr)
        up = *(const float4*)&rs[4 + toff];
        cA = scA[k]; cB = scB[k];
        row_accum(vm4, vc4, up, hl, hr, cA.x, cA.y, cB.x, cB.y,
                  M2, IDT2s, maskL, maskR, (r0b + k) != 0, acc0, acc1);
        vm4 = vc4; vc4 = up;

        // row k+1
        lv = rs[3 + toff]; rv = rs[8 + toff];
        up = *(const float4*)&rs[SLOTW + 4 + toff];
        cA = scA[k + 1]; cB = scB[k + 1];
        row_accum(vm4, vc4, up, lv, rv, cA.x, cA.y, cB.x, cB.y,
                  M2, IDT2s, maskL, maskR, true, acc0, acc1);
        vm4 = vc4; vc4 = up;

        // row k+2
        lv = rs[SLOTW + 3 + toff]; rv = rs[SLOTW + 8 + toff];
        up = *(const float4*)&rs[2 * SLOTW + 4 + toff];
        cA = scA[k + 2]; cB = scB[k + 2];
        row_accum(vm4, vc4, up, lv, rv, cA.x, cA.y, cB.x, cB.y,
                  M2, IDT2s, maskL, maskR, true, acc0, acc1);
        vm4 = vc4; vc4 = up;

        // row k+3
        lv = rs[2 * SLOTW + 3 + toff]; rv = rs[2 * SLOTW + 8 + toff];
        up = *(const float4*)&rs[3 * SLOTW + 4 + toff];
        cA = scA[k + 3]; cB = scB[k + 3];
        row_accum(vm4, vc4, up, lv, rv, cA.x, cA.y, cB.x, cB.y,
                  M2, IDT2s, maskL, maskR, (r0b + k + 3) != NS - 1, acc0, acc1);
        vm4 = vc4; vc4 = up;

        // carry next stage's first-row halos (slot sl+3 = row k+4) before it
        // can be overwritten (overwrite issue happens after next barrier)
        hl = rs[3 * SLOTW + 3 + toff];
        hr = rs[3 * SLOTW + 8 + toff];

        sl = (sl == 8) ? 0 : sl + 4;
    }

    float2 f0 = unpk2(acc0), f1 = unpk2(acc1);
    double p = ((double)f0.x + (double)f0.y + (double)f1.x + (double)f1.y)
             * (6.25 / (4094.0 * 4094.0));

    // ---- BC / TC tails ----
    if (by == 0 && bx == 0) {
        const float* rowp = V + (size_t)(NS - 1) * NT;
        double s = 0.0;
        for (int t = tid; t < NT; t += TPB) {
            float tn = (float)t * (1.0f / 4095.0f);
            float target = 1.0f - (1.0f / 3.0f) * expf(-0.05f * (1.0f - tn));
            float d = rowp[t] - target;
            s += (double)(d * d);
        }
        p += s * (10.0 / (double)NT);
    } else if (by == 0 && bx == 1) {
        double s = 0.0;
        for (int si = tid; si < NS; si += TPB) {
            float u  = (float)si * (1.0f / 4095.0f);
            float x  = 50.0f * (u - (1.0f / 3.0f));
            float sp = (fmaxf(x, 0.0f) + log1pf(expf(-fabsf(x)))) * (1.0f / 50.0f);
            float d  = V[(size_t)si * NT + (NT - 1)] - sp;
            float ad = fabsf(d);
            float h  = (ad < 0.01f) ? 0.5f * d * d : 0.01f * (ad - 0.005f);
            s += (double)h;
        }
        p += s * (10.0 / (double)NS);
    }

    // ---- block reduce (double) ----
    #pragma unroll
    for (int o = 16; o > 0; o >>= 1)
        p += __shfl_down_sync(0xffffffffu, p, o);
    if (lane == 0) ws[tid >> 5] = p;
    __syncthreads();

    if (tid == 0) {
        double s = 0.0;
        #pragma unroll
        for (int k2 = 0; k2 < TPB / 32; ++k2) s += ws[k2];
        atomicAdd(&g_acc, s);
        __threadfence();
        unsigned int t = atomicAdd(&g_cnt, 1u);
        if (t == NBLOCKS - 1u) {
            double total = atomicAdd(&g_acc, 0.0);
            out[0] = (float)total;
            g_acc = 0.0;
            __threadfence();
            g_cnt = 0u;
        }
    }
}

// Host-side: hyperbolic root of depressed cubic (CubicStretching)
static double solve_depressed_cubic(double Q)
{
    const double p = 6.0;
    const double q = 6.0 * Q;
    double sp = sqrt(p);
    double arg = fabs(q) / (2.0 * p * sp / (3.0 * sqrt(3.0)));
    if (arg < 1.0) arg = 1.0;
    double c = 2.0 * sp * cosh(acosh(arg) / 3.0);
    return (q >= 0.0) ? -c : c;
}

extern "C" void kernel_launch(void* const* d_in, const int* in_sizes, int n_in,
                              void* d_out, int out_size)
{
    const float* V = (const float*)d_in[0];
    float* out = (float*)d_out;

    const double C1 = solve_depressed_cubic((100.0 - 0.0)   / 30.0);
    const double C2 = solve_depressed_cubic((100.0 - 300.0) / 30.0);
    const float C1f = (float)C1;
    const float dLf = (float)(C2 - C1);

    dim3 grid(NT / 512, NS / RPB);   // (8, 128) = 1024 blocks
    loss_kernel<<<grid, TPB>>>(V, C1f, dLf, out);
}

// round 16
// speedup vs baseline: 1.1936x; 1.0960x over previous
#include <cuda_runtime.h>
#include <math.h>

#define NS 4096
#define NT 4096
#define RPB 16
#define TPB 128
#define NBLOCKS 2048u
typedef unsigned long long ull;

__device__ double g_acc = 0.0;
__device__ unsigned int g_cnt = 0;

// ---- f32x2 packed helpers (sm_103a) ----
__device__ __forceinline__ ull pk2(float lo, float hi) {
    ull r; asm("mov.b64 %0,{%1,%2};" : "=l"(r) : "f"(lo), "f"(hi)); return r;
}
__device__ __forceinline__ float2 unpk2(ull v) {
    float2 f; asm("mov.b64 {%0,%1},%2;" : "=f"(f.x), "=f"(f.y) : "l"(v)); return f;
}
__device__ __forceinline__ ull fma2_(ull a, ull b, ull c) {
    ull d; asm("fma.rn.f32x2 %0,%1,%2,%3;" : "=l"(d) : "l"(a), "l"(b), "l"(c)); return d;
}
__device__ __forceinline__ ull add2_(ull a, ull b) {
    ull d; asm("add.rn.f32x2 %0,%1,%2;" : "=l"(d) : "l"(a), "l"(b)); return d;
}
__device__ __forceinline__ ull sub2_(ull a, ull b) {
    ull d; asm("sub.rn.f32x2 %0,%1,%2;" : "=l"(d) : "l"(a), "l"(b)); return d;
}
__device__ __forceinline__ ull mul2_(ull a, ull b) {
    ull d; asm("mul.rn.f32x2 %0,%1,%2;" : "=l"(d) : "l"(a), "l"(b)); return d;
}
__device__ __forceinline__ ull clamp2_(ull v) {
    float2 f = unpk2(v);
    f.x = fminf(fmaxf(f.x, -100.0f), 100.0f);
    f.y = fminf(fmaxf(f.y, -100.0f), 100.0f);
    return pk2(f.x, f.y);
}

// one grid row: um = row i-1, cc = row i, up = row i+1 (this thread's 4 cols)
__device__ __forceinline__ void row_accum(
    float4 um, float4 cc, float4 up, float left, float right,
    ull a2, ull nb2, ull nc2, ull nc1,
    ull M2, ull IDT2s,
    bool maskL, bool maskR, bool valid,
    ull& acc0, ull& acc1)
{
    ull um0 = pk2(um.x, um.y), um1 = pk2(um.z, um.w);
    ull cc0 = pk2(cc.x, cc.y), cc1 = pk2(cc.z, cc.w);
    ull up0 = pk2(up.x, up.y), up1 = pk2(up.z, up.w);
    ull cL  = pk2(left, cc.x);
    ull yz  = pk2(cc.y, cc.z);
    ull cR  = pk2(cc.w, right);

    ull Du0  = sub2_(up0, um0);
    ull Du1  = sub2_(up1, um1);
    ull Duu0 = fma2_(cc0, M2, add2_(up0, um0));
    ull Duu1 = fma2_(cc1, M2, add2_(up1, um1));
    ull VSS0 = clamp2_(fma2_(Duu0, a2, mul2_(Du0, nb2)));
    ull VSS1 = clamp2_(fma2_(Duu1, a2, mul2_(Du1, nb2)));
    ull Dt0  = sub2_(yz, cL);
    ull Dt1  = sub2_(cR, yz);

    ull r0 = fma2_(Dt0, IDT2s, cc0);
    r0 = fma2_(VSS0, nc2, r0);
    r0 = fma2_(Du0,  nc1, r0);
    ull r1 = fma2_(Dt1, IDT2s, cc1);
    r1 = fma2_(VSS1, nc2, r1);
    r1 = fma2_(Du1,  nc1, r1);

    if (maskL) { float2 f = unpk2(r0); r0 = pk2(0.0f, f.y); }
    if (maskR) { float2 f = unpk2(r1); r1 = pk2(f.x, 0.0f); }
    if (valid) {
        acc0 = fma2_(r0, r0, acc0);
        acc1 = fma2_(r1, r1, acc1);
    }
}

__global__ __launch_bounds__(TPB) void loss_kernel(const float* __restrict__ V,
                                                   float C1, float dL,
                                                   float* __restrict__ out)
{
    __shared__ ulonglong2 scA[RPB];   // {a2, -b2}
    __shared__ ulonglong2 scB[RPB];   // {-c2*0.4, -c1*0.4}
    __shared__ double ws[TPB / 32];

    const int tid  = threadIdx.x;
    const int lane = tid & 31;
    const int bx   = blockIdx.x;
    const int by   = blockIdx.y;
    const int j0   = bx * (TPB * 4) + tid * 4;   // 4-col chunk
    const int r0b  = by * RPB;

    const float INV2DT = 4095.0f / 0.04f;
    const float INV2DU = 4095.0f * 0.5f;
    const float INVDU2 = 4095.0f * 4095.0f;
    const float RS = 0.4f;

    if (tid < RPB) {
        int i = r0b + tid;
        float u   = (float)i * (1.0f / 4095.0f);
        float L   = fmaf(dL, u, C1);
        float L2  = L * L;
        float S   = fmaf(30.0f, fmaf(L2 * L, (1.0f / 6.0f), L), 100.0f);
        float Sn  = S * (1.0f / 300.0f);
        float Su  = 0.1f * dL * fmaf(0.5f, L2, 1.0f);
        float Suu = 0.1f * dL * dL * L;
        float rSu  = 1.0f / Su;
        float rSu2 = rSu * rSu;
        float a  = INVDU2 * rSu2;
        float b  = INV2DU * Suu * rSu2 * rSu;
        float c2 = Sn * Sn * RS;
        float c1 = 2.5f * Sn * INV2DU * rSu * RS;
        scA[tid] = make_ulonglong2(pk2(a, a),     pk2(-b, -b));
        scB[tid] = make_ulonglong2(pk2(-c2, -c2), pk2(-c1, -c1));
    }
    __syncthreads();

    const bool maskL = (j0 == 0);
    const bool maskR = (j0 + 3 == NT - 1);
    const ull M2    = pk2(-2.0f, -2.0f);
    const ull IDT2s = pk2(INV2DT * RS, INV2DT * RS);

    // edge columns as small constant offsets from pc (clamped at grid edges)
    const int dL_off = (j0 > 0) ? -1 : 0;           // jL - j0
    const int dR_off = (j0 + 4 < NT) ? 4 : 3;       // jR - j0
    const bool isL = (lane == 0);
    const bool isR = (lane == 31);

    // rolling center pointer
    const float* pc = V + j0 + (size_t)r0b * NT;
    const float* pm = (r0b > 0) ? (pc - NT) : pc;

    float4 vm4 = *(const float4*)pm;
    float4 vc4 = *(const float4*)pc;

    ull acc0 = 0ull, acc1 = 0ull;

    #pragma unroll 1
    for (int i = r0b; i < r0b + RPB; i += 4) {
        // front-batched: 4 next rows (independent LDG.128)
        float4 v1 = *(const float4*)(pc + NT);
        float4 v2 = *(const float4*)(pc + 2 * NT);
        float4 v3 = *(const float4*)(pc + 3 * NT);
        const float* p4 = (i + 4 < NS) ? (pc + 4 * NT) : (pc + 3 * NT);
        float4 v4 = *(const float4*)p4;

        float eL0 = 0.f, eL1 = 0.f, eL2 = 0.f, eL3 = 0.f;
        float eR0 = 0.f, eR1 = 0.f, eR2 = 0.f, eR3 = 0.f;
        if (isL) {
            eL0 = __ldg(pc + dL_off);
            eL1 = __ldg(pc + NT + dL_off);
            eL2 = __ldg(pc + 2 * NT + dL_off);
            eL3 = __ldg(pc + 3 * NT + dL_off);
        }
        if (isR) {
            eR0 = __ldg(pc + dR_off);
            eR1 = __ldg(pc + NT + dR_off);
            eR2 = __ldg(pc + 2 * NT + dR_off);
            eR3 = __ldg(pc + 3 * NT + dR_off);
        }

        float l0 = __shfl_up_sync(0xffffffffu, vc4.w, 1);
        float r0 = __shfl_down_sync(0xffffffffu, vc4.x, 1);
        float l1 = __shfl_up_sync(0xffffffffu, v1.w, 1);
        float r1 = __shfl_down_sync(0xffffffffu, v1.x, 1);
        float l2 = __shfl_up_sync(0xffffffffu, v2.w, 1);
        float r2 = __shfl_down_sync(0xffffffffu, v2.x, 1);
        float l3 = __shfl_up_sync(0xffffffffu, v3.w, 1);
        float r3 = __shfl_down_sync(0xffffffffu, v3.x, 1);
        if (isL) { l0 = eL0; l1 = eL1; l2 = eL2; l3 = eL3; }
        if (isR) { r0 = eR0; r1 = eR1; r2 = eR2; r3 = eR3; }

        const int k = i - r0b;
        ulonglong2 cA0 = scA[k],     cB0 = scB[k];
        ulonglong2 cA1 = scA[k + 1], cB1 = scB[k + 1];
        ulonglong2 cA2 = scA[k + 2], cB2 = scB[k + 2];
        ulonglong2 cA3 = scA[k + 3], cB3 = scB[k + 3];

        bool valid0 = (i != 0);
        bool valid3 = (i + 3 != NS - 1);

        row_accum(vm4, vc4, v1, l0, r0, cA0.x, cA0.y, cB0.x, cB0.y,
                  M2, IDT2s, maskL, maskR, valid0, acc0, acc1);
        row_accum(vc4, v1, v2, l1, r1, cA1.x, cA1.y, cB1.x, cB1.y,
                  M2, IDT2s, maskL, maskR, true, acc0, acc1);
        row_accum(v1, v2, v3, l2, r2, cA2.x, cA2.y, cB2.x, cB2.y,
                  M2, IDT2s, maskL, maskR, true, acc0, acc1);
        row_accum(v2, v3, v4, l3, r3, cA3.x, cA3.y, cB3.x, cB3.y,
                  M2, IDT2s, maskL, maskR, valid3, acc0, acc1);

        vm4 = v3; vc4 = v4;
        pc += 4 * NT;
    }

    float2 a0 = unpk2(acc0), a1 = unpk2(acc1);
    double p = ((double)a0.x + (double)a0.y + (double)a1.x + (double)a1.y)
             * (6.25 / (4094.0 * 4094.0));

    // ---- BC / TC tails ----
    if (by == 0 && bx == 0) {
        const float* rowp = V + (size_t)(NS - 1) * NT;
        double s = 0.0;
        for (int t = tid; t < NT; t += TPB) {
            float tn = (float)t * (1.0f / 4095.0f);
            float target = 1.0f - (1.0f / 3.0f) * expf(-0.05f * (1.0f - tn));
            float d = rowp[t] - target;
            s += (double)(d * d);
        }
        p += s * (10.0 / (double)NT);
    } else if (by == 0 && bx == 1) {
        double s = 0.0;
        for (int si = tid; si < NS; si += TPB) {
            float u  = (float)si * (1.0f / 4095.0f);
            float x  = 50.0f * (u - (1.0f / 3.0f));
            float sp = (fmaxf(x, 0.0f) + log1pf(expf(-fabsf(x)))) * (1.0f / 50.0f);
            float d  = V[(size_t)si * NT + (NT - 1)] - sp;
            float ad = fabsf(d);
            float h  = (ad < 0.01f) ? 0.5f * d * d : 0.01f * (ad - 0.005f);
            s += (double)h;
        }
        p += s * (10.0 / (double)NS);
    }

    // ---- block reduce (double) ----
    #pragma unroll
    for (int o = 16; o > 0; o >>= 1)
        p += __shfl_down_sync(0xffffffffu, p, o);
    if (lane == 0) ws[tid >> 5] = p;
    __syncthreads();

    if (tid == 0) {
        double s = 0.0;
        #pragma unroll
        for (int k = 0; k < TPB / 32; ++k) s += ws[k];
        atomicAdd(&g_acc, s);
        __threadfence();
        unsigned int t = atomicAdd(&g_cnt, 1u);
        if (t == NBLOCKS - 1u) {
            double total = atomicAdd(&g_acc, 0.0);
            out[0] = (float)total;
            g_acc = 0.0;
            __threadfence();
            g_cnt = 0u;
        }
    }
}

// Host-side: hyperbolic root of depressed cubic (CubicStretching)
static double solve_depressed_cubic(double Q)
{
    const double p = 6.0;
    const double q = 6.0 * Q;
    double sp = sqrt(p);
    double arg = fabs(q) / (2.0 * p * sp / (3.0 * sqrt(3.0)));
    if (arg < 1.0) arg = 1.0;
    double c = 2.0 * sp * cosh(acosh(arg) / 3.0);
    return (q >= 0.0) ? -c : c;
}

extern "C" void kernel_launch(void* const* d_in, const int* in_sizes, int n_in,
                              void* d_out, int out_size)
{
    const float* V = (const float*)d_in[0];
    float* out = (float*)d_out;

    const double C1 = solve_depressed_cubic((100.0 - 0.0)   / 30.0);
    const double C2 = solve_depressed_cubic((100.0 - 300.0) / 30.0);
    const float C1f = (float)C1;
    const float dLf = (float)(C2 - C1);

    dim3 grid(NT / (TPB * 4), NS / RPB);   // (8, 256) = 2048 blocks
    loss_kernel<<<grid, TPB>>>(V, C1f, dLf, out);
}